// round 1
// baseline (speedup 1.0000x reference)
#include <cuda_runtime.h>

// Problem constants (shapes fixed by the dataset)
#define NHID 64
#define EXTD 32
#define KTOT 96          // NHID + EXTD, inner dim of fused GEMM
#define MAXN 50000       // max node count for device scratch
#define TILE_E 64        // edges per block tile
#define SA_LD 68         // padded leading dim for transposed A tile

// Device scratch (allocation-free rule: __device__ globals)
__device__ __align__(16) float g_M[192 * 64];      // W1 @ W2[:64]
__device__ __align__(16) float g_B[KTOT * 64];     // [Mb ; W2b], [k][col]
__device__ __align__(16) float g_c[64];            // b1 @ W2[:64] + b2
__device__ __align__(16) float g_Pa[MAXN * 64];    // h @ Ma
__device__ __align__(16) float g_Pc[MAXN * 64];    // h @ Mc

// ---------------------------------------------------------------------------
// Kernel 0: compose M = W1 @ W2a, c = b1 @ W2a + b2, and Bcat. Single block.
// ---------------------------------------------------------------------------
__global__ void compose_kernel(const float* __restrict__ W1,
                               const float* __restrict__ b1,
                               const float* __restrict__ W2,
                               const float* __restrict__ b2) {
    __shared__ float sW2a[64 * 64];
    int tid = threadIdx.x;
    for (int i = tid; i < 64 * 64; i += blockDim.x) sW2a[i] = W2[i];
    __syncthreads();

    for (int idx = tid; idx < 192 * 64; idx += blockDim.x) {
        int r = idx >> 6, j = idx & 63;
        float s = 0.f;
#pragma unroll 8
        for (int k = 0; k < 64; ++k) s += W1[r * 64 + k] * sW2a[k * 64 + j];
        g_M[idx] = s;
    }
    if (tid < 64) {
        float s = b2[tid];
        for (int k = 0; k < 64; ++k) s += b1[k] * sW2a[k * 64 + tid];
        g_c[tid] = s;
    }
    __syncthreads();  // orders g_M global writes within the block

    for (int idx = tid; idx < KTOT * 64; idx += blockDim.x) {
        int k = idx >> 6, j = idx & 63;
        g_B[idx] = (k < 64) ? g_M[(64 + k) * 64 + j] : W2[k * 64 + j];
    }
}

// ---------------------------------------------------------------------------
// Kernel 1: node projections Pa = h @ Ma, Pc = h @ Mc. Warp per node.
// ---------------------------------------------------------------------------
__global__ __launch_bounds__(256) void nodeproj_kernel(const float* __restrict__ h,
                                                       int nNodes) {
    __shared__ float sMa[64 * 64];
    __shared__ float sMc[64 * 64];
    int tid = threadIdx.x;
    for (int i = tid; i < 64 * 64; i += blockDim.x) {
        sMa[i] = g_M[i];
        sMc[i] = g_M[128 * 64 + i];
    }
    __syncthreads();

    int warp = tid >> 5, lane = tid & 31;
    int n = blockIdx.x * 8 + warp;
    if (n >= nNodes || n >= MAXN) return;

    float h0 = h[n * 64 + lane];
    float h1 = h[n * 64 + 32 + lane];
    float a0 = 0.f, a1 = 0.f, c0 = 0.f, c1 = 0.f;
#pragma unroll
    for (int k = 0; k < 64; ++k) {
        float hk = __shfl_sync(0xffffffffu, (k < 32) ? h0 : h1, k & 31);
        a0 += hk * sMa[k * 64 + lane];
        a1 += hk * sMa[k * 64 + 32 + lane];
        c0 += hk * sMc[k * 64 + lane];
        c1 += hk * sMc[k * 64 + 32 + lane];
    }
    g_Pa[n * 64 + lane] = a0;
    g_Pa[n * 64 + 32 + lane] = a1;
    g_Pc[n * 64 + lane] = c0;
    g_Pc[n * 64 + 32 + lane] = c1;
}

// ---------------------------------------------------------------------------
// Kernel 2: main edge kernel.
// out[e] = relu( Pa[src[e]] + Pc[dst[e]] + [e_h[e], ext[e]] @ Bcat + c )
// Tile: 64 edges x 64 out cols, 256 threads, 4x4 micro-tile per thread.
// ---------------------------------------------------------------------------
__global__ __launch_bounds__(256) void edge_kernel(const float* __restrict__ e_h,
                                                   const float* __restrict__ ext,
                                                   const int* __restrict__ src,
                                                   const int* __restrict__ dst,
                                                   float* __restrict__ out,
                                                   int E) {
    extern __shared__ float smem[];
    float* sA = smem;                         // [KTOT][SA_LD] transposed inputs
    float* sB = smem + KTOT * SA_LD;          // [KTOT][64] weights
    int* ssrc = (int*)(sB + KTOT * 64);       // [64]
    int* sdst = ssrc + TILE_E;                // [64]

    int tid = threadIdx.x;
    int base = blockIdx.x * TILE_E;

    // Load e_h part of A (64 edges x 64 feats), transposed into sA[k][e]
#pragma unroll
    for (int it = 0; it < 4; ++it) {
        int p4 = tid + it * 256;              // 0..1023 float4s
        int e = p4 >> 4;
        int k0 = (p4 & 15) << 2;
        int ge = base + e;
        float4 v = make_float4(0.f, 0.f, 0.f, 0.f);
        if (ge < E) v = *(const float4*)&e_h[(long)ge * 64 + k0];
        sA[(k0 + 0) * SA_LD + e] = v.x;
        sA[(k0 + 1) * SA_LD + e] = v.y;
        sA[(k0 + 2) * SA_LD + e] = v.z;
        sA[(k0 + 3) * SA_LD + e] = v.w;
    }
    // Load ext part of A (64 edges x 32 feats) into sA rows 64..95
#pragma unroll
    for (int it = 0; it < 2; ++it) {
        int p4 = tid + it * 256;              // 0..511 float4s
        int e = p4 >> 3;
        int k0 = (p4 & 7) << 2;
        int ge = base + e;
        float4 v = make_float4(0.f, 0.f, 0.f, 0.f);
        if (ge < E) v = *(const float4*)&ext[(long)ge * 32 + k0];
        sA[(64 + k0 + 0) * SA_LD + e] = v.x;
        sA[(64 + k0 + 1) * SA_LD + e] = v.y;
        sA[(64 + k0 + 2) * SA_LD + e] = v.z;
        sA[(64 + k0 + 3) * SA_LD + e] = v.w;
    }
    // Load Bcat (96x64) straight copy
#pragma unroll
    for (int it = 0; it < 6; ++it) {
        int p4 = tid + it * 256;              // 0..1535 float4s
        float4 v = *(const float4*)&g_B[p4 * 4];
        *(float4*)&sB[p4 * 4] = v;
    }
    if (tid < TILE_E) {
        int ge = base + tid;
        ssrc[tid] = (ge < E) ? src[ge] : 0;
        sdst[tid] = (ge < E) ? dst[ge] : 0;
    }
    __syncthreads();

    int er = tid & 15;       // edge group: edges er*4 .. er*4+3
    int cc = tid >> 4;       // col group:  cols  cc*4 .. cc*4+3
    int aoff = er * 4;
    int boff = cc * 4;

    float acc[16];
#pragma unroll
    for (int i = 0; i < 16; ++i) acc[i] = 0.f;

#pragma unroll 4
    for (int k = 0; k < KTOT; ++k) {
        float4 a = *(const float4*)&sA[k * SA_LD + aoff];
        float4 b = *(const float4*)&sB[k * 64 + boff];
        acc[0]  += a.x * b.x; acc[1]  += a.x * b.y; acc[2]  += a.x * b.z; acc[3]  += a.x * b.w;
        acc[4]  += a.y * b.x; acc[5]  += a.y * b.y; acc[6]  += a.y * b.z; acc[7]  += a.y * b.w;
        acc[8]  += a.z * b.x; acc[9]  += a.z * b.y; acc[10] += a.z * b.z; acc[11] += a.z * b.w;
        acc[12] += a.w * b.x; acc[13] += a.w * b.y; acc[14] += a.w * b.z; acc[15] += a.w * b.w;
    }

    float4 cb = *(const float4*)&g_c[boff];
#pragma unroll
    for (int i = 0; i < 4; ++i) {
        int le = er * 4 + i;
        int ge = base + le;
        if (ge < E) {
            int s = ssrc[le];
            int d = sdst[le];
            float4 pa = *(const float4*)&g_Pa[s * 64 + boff];
            float4 pc = *(const float4*)&g_Pc[d * 64 + boff];
            float4 o;
            o.x = fmaxf(acc[i * 4 + 0] + pa.x + pc.x + cb.x, 0.f);
            o.y = fmaxf(acc[i * 4 + 1] + pa.y + pc.y + cb.y, 0.f);
            o.z = fmaxf(acc[i * 4 + 2] + pa.z + pc.z + cb.z, 0.f);
            o.w = fmaxf(acc[i * 4 + 3] + pa.w + pc.w + cb.w, 0.f);
            *(float4*)&out[(long)ge * 64 + boff] = o;
        }
    }
}

// ---------------------------------------------------------------------------
// Launch
// ---------------------------------------------------------------------------
extern "C" void kernel_launch(void* const* d_in, const int* in_sizes, int n_in,
                              void* d_out, int out_size) {
    const float* h   = (const float*)d_in[0];
    const float* e_h = (const float*)d_in[1];
    const float* ext = (const float*)d_in[2];
    const float* W1  = (const float*)d_in[3];
    const float* b1  = (const float*)d_in[4];
    const float* W2  = (const float*)d_in[5];
    const float* b2  = (const float*)d_in[6];
    const int* src   = (const int*)d_in[7];
    const int* dst   = (const int*)d_in[8];
    float* out = (float*)d_out;

    int E = in_sizes[7];
    int N = in_sizes[0] / NHID;

    const int smem_bytes = (KTOT * SA_LD + KTOT * 64) * (int)sizeof(float)
                           + 2 * TILE_E * (int)sizeof(int);
    cudaFuncSetAttribute(edge_kernel, cudaFuncAttributeMaxDynamicSharedMemorySize,
                         smem_bytes);

    compose_kernel<<<1, 256>>>(W1, b1, W2, b2);
    nodeproj_kernel<<<(N + 7) / 8, 256>>>(h, N);
    edge_kernel<<<(E + TILE_E - 1) / TILE_E, 256, smem_bytes>>>(e_h, ext, src, dst, out, E);
}

// round 2
// speedup vs baseline: 1.4124x; 1.4124x over previous
#include <cuda_runtime.h>

typedef unsigned long long ull;

#define NHID 64
#define EXTD 32
#define KTOT 96
#define K2TOT 48          // KTOT/2 packed-k steps
#define MAXN 50000
#define TILE_E 128
#define LD2 130           // padded leading dim of A tile in float2 units

// Device scratch (allocation-free rule)
__device__ __align__(16) float g_M[192 * 64];      // W1 @ W2[:64]
__device__ __align__(16) float g_B[KTOT * 64];     // [Mb ; W2b] row-major [k][col]
__device__ __align__(16) float g_c[64];            // b1 @ W2[:64] + b2
__device__ __align__(16) float g_Pa[MAXN * 64];    // h @ Ma
__device__ __align__(16) float g_Pc[MAXN * 64];    // h @ Mc

__device__ __forceinline__ ull ffma2(ull a, ull b, ull c) {
    ull d;
    asm("fma.rn.f32x2 %0, %1, %2, %3;" : "=l"(d) : "l"(a), "l"(b), "l"(c));
    return d;
}
__device__ __forceinline__ ull pack2(float x, float y) {
    ull r;
    asm("mov.b64 %0, {%1, %2};" : "=l"(r) : "f"(x), "f"(y));
    return r;
}
__device__ __forceinline__ float2 unpack2(ull v) {
    float2 f;
    asm("mov.b64 {%0, %1}, %2;" : "=f"(f.x), "=f"(f.y) : "l"(v));
    return f;
}

// ---------------------------------------------------------------------------
// Kernel 0: compose. Fully parallel: one output element per thread.
// items: [0, 12288)           -> g_M[r][j] (and g_B[r-64][j] when 64<=r<128)
//        [12288, 12288+2048)  -> g_B[64+k][j] = W2[64+k][j]
//        [14336, 14336+64)    -> g_c[j]
// ---------------------------------------------------------------------------
__global__ __launch_bounds__(256) void compose_kernel(const float* __restrict__ W1,
                                                      const float* __restrict__ b1,
                                                      const float* __restrict__ W2,
                                                      const float* __restrict__ b2) {
    int idx = blockIdx.x * blockDim.x + threadIdx.x;
    if (idx < 12288) {
        int r = idx >> 6, j = idx & 63;
        float s = 0.f;
#pragma unroll 16
        for (int k = 0; k < 64; ++k) s += W1[r * 64 + k] * W2[k * 64 + j];
        g_M[idx] = s;
        if (r >= 64 && r < 128) g_B[(r - 64) * 64 + j] = s;
    } else if (idx < 14336) {
        int t = idx - 12288;           // 0..2047 -> rows 64..95 of B
        g_B[64 * 64 + t] = W2[64 * 64 + t];
    } else if (idx < 14400) {
        int j = idx - 14336;
        float s = b2[j];
#pragma unroll 16
        for (int k = 0; k < 64; ++k) s += b1[k] * W2[k * 64 + j];
        g_c[j] = s;
    }
}

// ---------------------------------------------------------------------------
// Kernel 1: node projections Pa = h @ Ma, Pc = h @ Mc. Warp per node.
// ---------------------------------------------------------------------------
__global__ __launch_bounds__(256) void nodeproj_kernel(const float* __restrict__ h,
                                                       int nNodes) {
    __shared__ float sMa[64 * 64];
    __shared__ float sMc[64 * 64];
    int tid = threadIdx.x;
    for (int i = tid; i < 64 * 64; i += blockDim.x) {
        sMa[i] = g_M[i];
        sMc[i] = g_M[128 * 64 + i];
    }
    __syncthreads();

    int warp = tid >> 5, lane = tid & 31;
    int n = blockIdx.x * 8 + warp;
    if (n >= nNodes || n >= MAXN) return;

    float h0 = h[n * 64 + lane];
    float h1 = h[n * 64 + 32 + lane];
    float a0 = 0.f, a1 = 0.f, c0 = 0.f, c1 = 0.f;
#pragma unroll
    for (int k = 0; k < 64; ++k) {
        float hk = __shfl_sync(0xffffffffu, (k < 32) ? h0 : h1, k & 31);
        a0 += hk * sMa[k * 64 + lane];
        a1 += hk * sMa[k * 64 + 32 + lane];
        c0 += hk * sMc[k * 64 + lane];
        c1 += hk * sMc[k * 64 + 32 + lane];
    }
    g_Pa[n * 64 + lane] = a0;
    g_Pa[n * 64 + 32 + lane] = a1;
    g_Pc[n * 64 + lane] = c0;
    g_Pc[n * 64 + 32 + lane] = c1;
}

// ---------------------------------------------------------------------------
// Kernel 2: edge GEMM with packed f32x2 FMA.
// out[e] = relu( Pa[src[e]] + Pc[dst[e]] + [e_h[e], ext[e]] @ Bcat + c )
// Tile: 128 edges x 64 cols. 256 threads. Micro-tile 4 edges x 8 cols.
// A stored k-pair interleaved: sA2[k2][e] = (a[2k2][e], a[2k2+1][e]).
// Warp layout: lane = edge-group, warp = col-group -> B loads broadcast.
// ---------------------------------------------------------------------------
__global__ __launch_bounds__(256, 2) void edge_kernel(const float* __restrict__ e_h,
                                                      const float* __restrict__ ext,
                                                      const int* __restrict__ src,
                                                      const int* __restrict__ dst,
                                                      float* __restrict__ out,
                                                      int E) {
    extern __shared__ __align__(16) char smem[];
    ull* sA2 = (ull*)smem;                         // [K2TOT][LD2]
    ull* sB2 = sA2 + K2TOT * LD2;                  // [K2TOT][64]
    int* ssrc = (int*)(sB2 + K2TOT * 64);          // [TILE_E]
    int* sdst = ssrc + TILE_E;

    int tid = threadIdx.x;
    int base = blockIdx.x * TILE_E;

    // ---- Load A: e_h part (128 edges x 64 feats) -> rows 0..31 of sA2
#pragma unroll
    for (int it = 0; it < 8; ++it) {
        int p = tid + it * 256;        // 0..2047 float4s
        int e = p >> 4;
        int k0 = (p & 15) << 2;
        int ge = base + e;
        float4 v = make_float4(0.f, 0.f, 0.f, 0.f);
        if (ge < E) v = *(const float4*)&e_h[(long)ge * 64 + k0];
        int k2 = k0 >> 1;
        sA2[k2 * LD2 + e] = pack2(v.x, v.y);
        sA2[(k2 + 1) * LD2 + e] = pack2(v.z, v.w);
    }
    // ---- Load A: ext part (128 edges x 32 feats) -> rows 32..47
#pragma unroll
    for (int it = 0; it < 4; ++it) {
        int p = tid + it * 256;        // 0..1023 float4s
        int e = p >> 3;
        int k0 = (p & 7) << 2;
        int ge = base + e;
        float4 v = make_float4(0.f, 0.f, 0.f, 0.f);
        if (ge < E) v = *(const float4*)&ext[(long)ge * 32 + k0];
        int k2 = 32 + (k0 >> 1);
        sA2[k2 * LD2 + e] = pack2(v.x, v.y);
        sA2[(k2 + 1) * LD2 + e] = pack2(v.z, v.w);
    }
    // ---- Load B packed: sB2[k2][c] = (B[2k2][c], B[2k2+1][c])
#pragma unroll
    for (int it = 0; it < 3; ++it) {
        int p = tid + it * 256;        // 0..767: 48 k2 x 16 col4-groups
        int k2 = p >> 4;
        int c4 = (p & 15) << 2;
        float4 r0 = *(const float4*)&g_B[(2 * k2) * 64 + c4];
        float4 r1 = *(const float4*)&g_B[(2 * k2 + 1) * 64 + c4];
        sB2[k2 * 64 + c4 + 0] = pack2(r0.x, r1.x);
        sB2[k2 * 64 + c4 + 1] = pack2(r0.y, r1.y);
        sB2[k2 * 64 + c4 + 2] = pack2(r0.z, r1.z);
        sB2[k2 * 64 + c4 + 3] = pack2(r0.w, r1.w);
    }
    if (tid < TILE_E) {
        int ge = base + tid;
        ssrc[tid] = (ge < E) ? src[ge] : 0;
        sdst[tid] = (ge < E) ? dst[ge] : 0;
    }
    __syncthreads();

    int eg = tid & 31;      // lane: edge group -> edges eg*2,eg*2+1,64+eg*2,64+eg*2+1
    int cg = tid >> 5;      // warp: col group -> cols cg*8 .. cg*8+7 (B broadcast)

    ull acc[4][8];
#pragma unroll
    for (int i = 0; i < 4; ++i)
#pragma unroll
        for (int j = 0; j < 8; ++j) acc[i][j] = 0ull;

#pragma unroll 4
    for (int k2 = 0; k2 < K2TOT; ++k2) {
        const ull* arow = sA2 + k2 * LD2;
        ulonglong2 a01 = *(const ulonglong2*)(arow + eg * 2);
        ulonglong2 a23 = *(const ulonglong2*)(arow + 64 + eg * 2);
        const ull* brow = sB2 + k2 * 64 + cg * 8;
        ulonglong2 b01 = *(const ulonglong2*)(brow + 0);
        ulonglong2 b23 = *(const ulonglong2*)(brow + 2);
        ulonglong2 b45 = *(const ulonglong2*)(brow + 4);
        ulonglong2 b67 = *(const ulonglong2*)(brow + 6);
        ull av[4] = {a01.x, a01.y, a23.x, a23.y};
        ull bv[8] = {b01.x, b01.y, b23.x, b23.y, b45.x, b45.y, b67.x, b67.y};
#pragma unroll
        for (int i = 0; i < 4; ++i)
#pragma unroll
            for (int j = 0; j < 8; ++j)
                acc[i][j] = ffma2(av[i], bv[j], acc[i][j]);
    }

    // ---- Epilogue: gather node projections, bias, relu, store
    float4 cb0 = *(const float4*)&g_c[cg * 8];
    float4 cb1 = *(const float4*)&g_c[cg * 8 + 4];
#pragma unroll
    for (int i = 0; i < 4; ++i) {
        int le = (i < 2) ? (eg * 2 + i) : (64 + eg * 2 + (i - 2));
        int ge = base + le;
        if (ge < E) {
            int s = ssrc[le];
            int d = sdst[le];
            const float* pa = &g_Pa[(long)s * 64 + cg * 8];
            const float* pc = &g_Pc[(long)d * 64 + cg * 8];
            float4 pa0 = *(const float4*)pa;
            float4 pa1 = *(const float4*)(pa + 4);
            float4 pc0 = *(const float4*)pc;
            float4 pc1 = *(const float4*)(pc + 4);
            float r[8];
#pragma unroll
            for (int j = 0; j < 8; ++j) {
                float2 f = unpack2(acc[i][j]);
                r[j] = f.x + f.y;
            }
            float4 o0, o1;
            o0.x = fmaxf(r[0] + pa0.x + pc0.x + cb0.x, 0.f);
            o0.y = fmaxf(r[1] + pa0.y + pc0.y + cb0.y, 0.f);
            o0.z = fmaxf(r[2] + pa0.z + pc0.z + cb0.z, 0.f);
            o0.w = fmaxf(r[3] + pa0.w + pc0.w + cb0.w, 0.f);
            o1.x = fmaxf(r[4] + pa1.x + pc1.x + cb1.x, 0.f);
            o1.y = fmaxf(r[5] + pa1.y + pc1.y + cb1.y, 0.f);
            o1.z = fmaxf(r[6] + pa1.z + pc1.z + cb1.z, 0.f);
            o1.w = fmaxf(r[7] + pa1.w + pc1.w + cb1.w, 0.f);
            float* op = &out[(long)ge * 64 + cg * 8];
            *(float4*)op = o0;
            *(float4*)(op + 4) = o1;
        }
    }
}

// ---------------------------------------------------------------------------
extern "C" void kernel_launch(void* const* d_in, const int* in_sizes, int n_in,
                              void* d_out, int out_size) {
    const float* h   = (const float*)d_in[0];
    const float* e_h = (const float*)d_in[1];
    const float* ext = (const float*)d_in[2];
    const float* W1  = (const float*)d_in[3];
    const float* b1  = (const float*)d_in[4];
    const float* W2  = (const float*)d_in[5];
    const float* b2  = (const float*)d_in[6];
    const int* src   = (const int*)d_in[7];
    const int* dst   = (const int*)d_in[8];
    float* out = (float*)d_out;

    int E = in_sizes[7];
    int N = in_sizes[0] / NHID;

    const int smem_bytes = (K2TOT * LD2 + K2TOT * 64) * (int)sizeof(ull)
                           + 2 * TILE_E * (int)sizeof(int);
    static int attr_done = 0;
    if (!attr_done) {
        cudaFuncSetAttribute(edge_kernel, cudaFuncAttributeMaxDynamicSharedMemorySize,
                             smem_bytes);
        attr_done = 1;
    }

    compose_kernel<<<(14400 + 255) / 256, 256>>>(W1, b1, W2, b2);
    nodeproj_kernel<<<(N + 7) / 8, 256>>>(h, N);
    edge_kernel<<<(E + TILE_E - 1) / TILE_E, 256, smem_bytes>>>(e_h, ext, src, dst, out, E);
}